// round 15
// baseline (speedup 1.0000x reference)
#include <cuda_runtime.h>
#include <cuda_bf16.h>
#include <cstdint>

#define Bsz 4096
#define Tst 128
#define NL  256
#define NSt 64
#define NOt 32
#define Vt  64
#define MT  32
#define XR  264        // x row stride (bf16)
#define NC2 8          // GEMM1 chunks per step (k16 each, per k-half)
#define SLG 36
#define W2R 264

typedef uint32_t u32;

__device__ __nv_bfloat16 g_w1h[(size_t)NSt * NL * NL];
__device__ __nv_bfloat16 g_w1l[(size_t)NSt * NL * NL];
__device__ __nv_bfloat16 g_w2h[(size_t)NSt * NOt * NL];
__device__ __nv_bfloat16 g_w2l[(size_t)NSt * NOt * NL];

__device__ __forceinline__ u32 s2u(const void* p) {
    return (u32)__cvta_generic_to_shared(p);
}
__device__ __forceinline__ void ldsm4(u32* r, u32 a) {
    asm volatile("ldmatrix.sync.aligned.m8n8.x4.shared.b16 {%0,%1,%2,%3}, [%4];"
        : "=r"(r[0]), "=r"(r[1]), "=r"(r[2]), "=r"(r[3]) : "r"(a));
}
__device__ __forceinline__ void mma16(float* c, const u32* a, u32 b0, u32 b1) {
    asm volatile("mma.sync.aligned.m16n8k16.row.col.f32.bf16.bf16.f32 "
        "{%0,%1,%2,%3},{%4,%5,%6,%7},{%8,%9},{%0,%1,%2,%3};"
        : "+f"(c[0]), "+f"(c[1]), "+f"(c[2]), "+f"(c[3])
        : "r"(a[0]), "r"(a[1]), "r"(a[2]), "r"(a[3]), "r"(b0), "r"(b1));
}
__device__ __forceinline__ void cpa16(u32 dst, const void* src) {
    asm volatile("cp.async.cg.shared.global [%0], [%1], 16;"
        :: "r"(dst), "l"(src) : "memory");
}
#define CPA_COMMIT() asm volatile("cp.async.commit_group;" ::: "memory")
#define CPA_WAIT2()  asm volatile("cp.async.wait_group 2;" ::: "memory")

__device__ __forceinline__ float ftanh(float x) {
    float t = __expf(-2.f * fabsf(x));
    float r = __fdividef(1.f - t, 1.f + t);
    return copysignf(r, x);
}
__device__ __forceinline__ void sp(__nv_bfloat16* xh, __nv_bfloat16* xl, int idx,
                                   float v0, float v1) {
    __nv_bfloat16 h0 = __float2bfloat16(v0), h1 = __float2bfloat16(v1);
    __nv_bfloat162 hp; hp.x = h0; hp.y = h1;
    *(__nv_bfloat162*)(xh + idx) = hp;
    __nv_bfloat162 lp;
    lp.x = __float2bfloat16(v0 - __bfloat162float(h0));
    lp.y = __float2bfloat16(v1 - __bfloat162float(h1));
    *(__nv_bfloat162*)(xl + idx) = lp;
}

// smem byte offsets (single x buffer; RS1/RS2 overlaid)
#define OB_XH  0        // [32][XR] bf16 = 16896
#define OB_XL  16896    // -> 33792
#define OB_W1S 33792    // 16 warps x 3 stages x 2048B = 98304 -> 132096
#define OB_W2H 132096   // 16896 -> 148992
#define OB_W2L 148992   // 16896 -> 165888
#define OB_RS  165888   // max(RS1 8x5120=40960, RS2 18432) -> 206848
#define OB_LG  206848   // 4608 -> 211456
#define OB_DON 211456   // 16 warps x 64 i32 = 4096 -> 215552
#define OB_B2  215552   // 128
#define OB_SQ  215680   // 512
#define SMEMB  216192

__global__ void split_w12(const float* __restrict__ W1, const float* __restrict__ W2) {
    const size_t n1 = (size_t)NSt * NL * NL;
    for (size_t i = blockIdx.x * blockDim.x + threadIdx.x; i < n1;
         i += (size_t)gridDim.x * blockDim.x) {
        float x = W1[i];
        __nv_bfloat16 h = __float2bfloat16(x);
        g_w1h[i] = h;
        g_w1l[i] = __float2bfloat16(x - __bfloat162float(h));
    }
    const size_t n2 = (size_t)NSt * NOt * NL;
    for (size_t i = blockIdx.x * blockDim.x + threadIdx.x; i < n2;
         i += (size_t)gridDim.x * blockDim.x) {
        float x = W2[i];
        __nv_bfloat16 h = __float2bfloat16(x);
        g_w2h[i] = h;
        g_w2l[i] = __float2bfloat16(x - __bfloat162float(h));
    }
}

__global__ void __launch_bounds__(512, 1) lalr_all(
    const float* __restrict__ latent0,
    const float* __restrict__ W1, const float* __restrict__ b1,
    const float* __restrict__ W2, const float* __restrict__ b2,
    const int*   __restrict__ state_seq, const int* __restrict__ out_idx,
    float* __restrict__ out)
{
    extern __shared__ char smc[];
    __nv_bfloat16* xh = (__nv_bfloat16*)(smc + OB_XH);
    __nv_bfloat16* xl = (__nv_bfloat16*)(smc + OB_XL);
    float* rs  = (float*)(smc + OB_RS);
    float* lg  = (float*)(smc + OB_LG);
    float* b2s = (float*)(smc + OB_B2);
    int*  sseq = (int*)(smc + OB_SQ);

    const int tid = threadIdx.x;
    const int w = tid >> 5, l = tid & 31;
    const int rowbase = blockIdx.x * MT;
    const int gid = l >> 2, tg = l & 3;

    // GEMM1 warp roles: nq = n-group (32 cols), kg = k-half (128)
    const int nq = w & 7, kg = w >> 3;

    // A fragment lane mapping (proven idiom)
    const int arow = l & 15;
    const int akof = (l >> 4) * 8;
    // B fragment lane mapping (proven idiom)
    const int bn = ((l >> 4) & 1) * 8 + (l & 7);
    const int bk = (l >> 3) & 1;
    // GEMM1 B read offsets in 1KB packed+swizzled stage (32 cols x 32B)
    const u32 bo0 = (u32)((bn * 32 + bk * 16) ^ (((bn >> 2) & 1) << 4));
    const u32 bo1 = (u32)(((16 + bn) * 32 + bk * 16) ^ (((bn >> 2) & 1) << 4));
    // W1 fill: lane l fills stage col l (32B hi + 32B lo)
    const u32 fil0 = (u32)((l * 32) ^ (((l >> 2) & 1) << 4));
    const u32 fil1 = fil0 ^ 16u;
    const u32 wstage = s2u(smc + OB_W1S + w * 6144);  // 3 stages x 2048B
    // W2 fill / GEMM2 mappings (R13-proven)
    const int bofs264 = (bn * W2R + bk * 8) * 2;
    const int o2 = tid & 31, kq2 = (tid >> 5) * 16;
    const int mi2 = w & 1, nh = (w >> 1) & 1, kg2 = w >> 2;

    // ---- init ----
    if (tid < Tst) sseq[tid] = state_seq[tid];
    {
        int r = tid >> 4, kc = (tid & 15) * 16;
        const float* src = latent0 + (size_t)(rowbase + r) * NL + kc;
        #pragma unroll
        for (int j = 0; j < 16; j += 2)
            sp(xh + r * XR + kc, xl + r * XR + kc, j, src[j], src[j + 1]);
    }
    __syncthreads();

    // W1 chunk issuer: chunk = k16 slice of this warp's (nq cols, kg k-half)
    auto issue_w1 = [&](int ig, size_t base, int stg) {
        if (ig < Tst * NC2) {
            size_t off = base + ((size_t)(ig & 7) << 4);
            u32 d = wstage + (u32)stg * 2048u;
            cpa16(d + fil0, g_w1h + off);
            cpa16(d + fil1, g_w1h + off + 8);
            cpa16(d + 1024 + fil0, g_w1l + off);
            cpa16(d + 1024 + fil1, g_w1l + off + 8);
        }
        CPA_COMMIT();
    };

    int s = sseq[0];
    size_t base_cur = ((size_t)s * NL + nq * 32 + l) * NL + kg * 128;
    issue_w1(0, base_cur, 0);
    issue_w1(1, base_cur, 1);
    int istg = 2, rstg = 0;   // rolling mod-3 stage counters

    // W2 prefetch for t=0
    const __nv_bfloat16* w2hsrc = g_w2h + ((size_t)s * NOt + o2) * NL + kq2;
    const __nv_bfloat16* w2lsrc = g_w2l + ((size_t)s * NOt + o2) * NL + kq2;
    uint4 qh0 = *(const uint4*)(w2hsrc);
    uint4 qh1 = *(const uint4*)(w2hsrc + 8);
    uint4 ql0 = *(const uint4*)(w2lsrc);
    uint4 ql1 = *(const uint4*)(w2lsrc + 8);
    float b2r = (tid < NOt) ? b2[s * NOt + tid] : 0.f;

    for (int t = 0; t < Tst; t++) {
        float2 bias[4];
        #pragma unroll
        for (int nj = 0; nj < 4; nj++)
            bias[nj] = *(const float2*)(b1 + s * NL + nq * 32 + nj * 8 + 2 * tg);
        int idxv = out_idx[s * NOt + l];
        const int s_nxt = sseq[(t + 1) & (Tst - 1)];
        const size_t base_nxt = ((size_t)s_nxt * NL + nq * 32 + l) * NL + kg * 128;

        // W2 -> smem (h/l); b2 -> smem   (prev readers gated by barrier D of t-1)
        {
            char* dh = smc + OB_W2H + (o2 * W2R + kq2) * 2;
            char* dl = smc + OB_W2L + (o2 * W2R + kq2) * 2;
            *(uint4*)(dh) = qh0; *(uint4*)(dh + 16) = qh1;
            *(uint4*)(dl) = ql0; *(uint4*)(dl + 16) = ql1;
        }
        if (tid < NOt) b2s[tid] = b2r;
        __syncwarp();

        // ---- GEMM1: warp = m32 x n32 x k128, 3-term split, 8 chunks ----
        float acc[2][4][4];
        #pragma unroll
        for (int mi = 0; mi < 2; mi++)
            #pragma unroll
            for (int nj = 0; nj < 4; nj++)
                #pragma unroll
                for (int q = 0; q < 4; q++) acc[mi][nj][q] = 0.f;

        const u32 aHb = s2u(xh + arow * XR + kg * 128 + akof);
        const u32 aLb = s2u(xl + arow * XR + kg * 128 + akof);

        #pragma unroll
        for (int kt = 0; kt < NC2; kt++) {
            const int g = t * NC2 + kt;
            issue_w1(g + 2, (kt + 2 < NC2) ? base_cur : base_nxt, istg);
            istg = (istg == 2) ? 0 : istg + 1;
            CPA_WAIT2();
            __syncwarp();

            const u32 ka = (u32)(kt * 32);
            u32 AH0[4], AH1[4], AL0[4], AL1[4], BH0[4], BH1[4], BL0[4], BL1[4];
            const u32 wb = wstage + (u32)rstg * 2048u;
            rstg = (rstg == 2) ? 0 : rstg + 1;
            ldsm4(BH0, wb + bo0);
            ldsm4(BH1, wb + bo1);
            ldsm4(BL0, wb + 1024 + bo0);
            ldsm4(BL1, wb + 1024 + bo1);
            ldsm4(AH0, aHb + ka);
            ldsm4(AH1, aHb + ka + 16 * XR * 2);
            ldsm4(AL0, aLb + ka);
            ldsm4(AL1, aLb + ka + 16 * XR * 2);

            // hh
            mma16(acc[0][0], AH0, BH0[0], BH0[1]); mma16(acc[0][1], AH0, BH0[2], BH0[3]);
            mma16(acc[0][2], AH0, BH1[0], BH1[1]); mma16(acc[0][3], AH0, BH1[2], BH1[3]);
            mma16(acc[1][0], AH1, BH0[0], BH0[1]); mma16(acc[1][1], AH1, BH0[2], BH0[3]);
            mma16(acc[1][2], AH1, BH1[0], BH1[1]); mma16(acc[1][3], AH1, BH1[2], BH1[3]);
            // hl
            mma16(acc[0][0], AH0, BL0[0], BL0[1]); mma16(acc[0][1], AH0, BL0[2], BL0[3]);
            mma16(acc[0][2], AH0, BL1[0], BL1[1]); mma16(acc[0][3], AH0, BL1[2], BL1[3]);
            mma16(acc[1][0], AH1, BL0[0], BL0[1]); mma16(acc[1][1], AH1, BL0[2], BL0[3]);
            mma16(acc[1][2], AH1, BL1[0], BL1[1]); mma16(acc[1][3], AH1, BL1[2], BL1[3]);
            // lh
            mma16(acc[0][0], AL0, BH0[0], BH0[1]); mma16(acc[0][1], AL0, BH0[2], BH0[3]);
            mma16(acc[0][2], AL0, BH1[0], BH1[1]); mma16(acc[0][3], AL0, BH1[2], BH1[3]);
            mma16(acc[1][0], AL1, BH0[0], BH0[1]); mma16(acc[1][1], AL1, BH0[2], BH0[3]);
            mma16(acc[1][2], AL1, BH1[0], BH1[1]); mma16(acc[1][3], AL1, BH1[2], BH1[3]);
        }

        // kg0 warps: publish partials to RS1 [nq][m32][40]
        if (kg == 0) {
            float* pr = rs + nq * 1280;
            #pragma unroll
            for (int mi = 0; mi < 2; mi++)
                #pragma unroll
                for (int nj = 0; nj < 4; nj++) {
                    float* dst = pr + (mi * 16 + gid) * 40 + nj * 8 + 2 * tg;
                    float2 lo; lo.x = acc[mi][nj][0]; lo.y = acc[mi][nj][1];
                    float2 hi; hi.x = acc[mi][nj][2]; hi.y = acc[mi][nj][3];
                    *(float2*)dst = lo;
                    *(float2*)(dst + 8 * 40) = hi;
                }
        }

        // W2/b2 prefetch for t+1
        w2hsrc = g_w2h + ((size_t)s_nxt * NOt + o2) * NL + kq2;
        w2lsrc = g_w2l + ((size_t)s_nxt * NOt + o2) * NL + kq2;
        qh0 = *(const uint4*)(w2hsrc);
        qh1 = *(const uint4*)(w2hsrc + 8);
        ql0 = *(const uint4*)(w2lsrc);
        ql1 = *(const uint4*)(w2lsrc + 8);
        b2r = (tid < NOt) ? b2[s_nxt * NOt + tid] : 0.f;
        s = s_nxt;
        base_cur = base_nxt;

        __syncthreads();   // A: x reads done; RS1 partials visible

        // kg1 warps: merge partials + tanh epilogue -> x in place
        if (kg == 1) {
            float* pr = rs + nq * 1280;
            #pragma unroll
            for (int mi = 0; mi < 2; mi++)
                #pragma unroll
                for (int nj = 0; nj < 4; nj++) {
                    float* src = pr + (mi * 16 + gid) * 40 + nj * 8 + 2 * tg;
                    float2 lo = *(const float2*)src;
                    float2 hi = *(const float2*)(src + 8 * 40);
                    float2 bb = bias[nj];
                    int cp = nq * 32 + nj * 8 + 2 * tg;
                    int r0 = mi * 16 + gid;
                    sp(xh, xl, r0 * XR + cp,
                       ftanh(acc[mi][nj][0] + lo.x + bb.x),
                       ftanh(acc[mi][nj][1] + lo.y + bb.y));
                    sp(xh, xl, (r0 + 8) * XR + cp,
                       ftanh(acc[mi][nj][2] + hi.x + bb.x),
                       ftanh(acc[mi][nj][3] + hi.y + bb.y));
                }
        }
        __syncthreads();   // B: x_{t+1} + w2/b2 smem ready; RS1 dead

        // ---- GEMM2 via MMA: warp = m16(mi2) x n16(nh) x k64(kg2), 3-term ----
        {
            float c2[2][4];
            #pragma unroll
            for (int j = 0; j < 2; j++)
                #pragma unroll
                for (int q = 0; q < 4; q++) c2[j][q] = 0.f;

            const u32 a2h = s2u(xh + (mi2 * 16 + arow) * XR + kg2 * 64 + akof);
            const u32 a2l = s2u(xl + (mi2 * 16 + arow) * XR + kg2 * 64 + akof);
            const u32 b2hB = s2u(smc + OB_W2H) + nh * 16 * W2R * 2 + bofs264 + kg2 * 128;
            const u32 b2lB = s2u(smc + OB_W2L) + nh * 16 * W2R * 2 + bofs264 + kg2 * 128;

            #pragma unroll
            for (int kc = 0; kc < 4; kc++) {
                const u32 kb = (u32)(kc * 32);
                u32 ah[4], al[4], bh[4], bl[4];
                ldsm4(ah, a2h + kb);
                ldsm4(al, a2l + kb);
                ldsm4(bh, b2hB + kb);
                ldsm4(bl, b2lB + kb);
                mma16(c2[0], ah, bh[0], bh[1]); mma16(c2[1], ah, bh[2], bh[3]);
                mma16(c2[0], ah, bl[0], bl[1]); mma16(c2[1], ah, bl[2], bl[3]);
                mma16(c2[0], al, bh[0], bh[1]); mma16(c2[1], al, bh[2], bh[3]);
            }
            #pragma unroll
            for (int j = 0; j < 2; j++) {
                float* dst = rs + (kg2 * 32 + mi2 * 16 + gid) * 36 + nh * 16 + j * 8 + 2 * tg;
                float2 lo; lo.x = c2[j][0]; lo.y = c2[j][1];
                float2 hi; hi.x = c2[j][2]; hi.y = c2[j][3];
                *(float2*)dst = lo;
                *(float2*)(dst + 8 * 36) = hi;
            }
        }
        __syncthreads();   // C: GEMM2 partials ready

        // ---- split-k reduce -> logits ----
        {
            int rrow = 2 * w + (l >> 4);
            int cc = (l & 15) * 2;
            float2 sum; sum.x = b2s[cc]; sum.y = b2s[cc + 1];
            #pragma unroll
            for (int kk = 0; kk < 4; kk++) {
                float2 v = *(const float2*)(rs + (kk * 32 + rrow) * 36 + cc);
                sum.x += v.x; sum.y += v.y;
            }
            *(float2*)(lg + rrow * SLG + cc) = sum;
        }
        __syncwarp();

        // ---- softmax (2 rows interleaved) + donor-table scatter + store ----
        {
            int* don = (int*)(smc + OB_DON) + w * 64;
            don[l] = -1; don[l + 32] = -1;
            __syncwarp();
            unsigned mset = __match_any_sync(0xffffffffu, idxv);
            bool leader = (31 - __clz(mset)) == l;
            if (leader) don[idxv] = l;
            __syncwarp();
            int d0 = don[2 * l], d1 = don[2 * l + 1];

            float v0 = lg[(2 * w) * SLG + l];
            float v1 = lg[(2 * w + 1) * SLG + l];
            float m0 = v0, m1 = v1;
            #pragma unroll
            for (int off = 16; off > 0; off >>= 1) {
                m0 = fmaxf(m0, __shfl_xor_sync(0xffffffffu, m0, off));
                m1 = fmaxf(m1, __shfl_xor_sync(0xffffffffu, m1, off));
            }
            float e0 = __expf(v0 - m0), e1 = __expf(v1 - m1);
            float s0 = e0, s1 = e1;
            #pragma unroll
            for (int off = 16; off > 0; off >>= 1) {
                s0 += __shfl_xor_sync(0xffffffffu, s0, off);
                s1 += __shfl_xor_sync(0xffffffffu, s1, off);
            }
            float p0 = __fdividef(e0, s0), p1 = __fdividef(e1, s1);

            float a0 = __shfl_sync(0xffffffffu, p0, d0 & 31);
            float a1 = __shfl_sync(0xffffffffu, p0, d1 & 31);
            float b0 = __shfl_sync(0xffffffffu, p1, d0 & 31);
            float b1v = __shfl_sync(0xffffffffu, p1, d1 & 31);
            float2 o0, o1;
            o0.x = (d0 >= 0) ? a0 : 0.f; o0.y = (d1 >= 0) ? a1 : 0.f;
            o1.x = (d0 >= 0) ? b0 : 0.f; o1.y = (d1 >= 0) ? b1v : 0.f;
            float* op0 = out + (size_t)(rowbase + 2 * w) * (Tst * Vt) + (size_t)t * Vt;
            *(float2*)(op0 + 2 * l) = o0;
            *(float2*)(op0 + (size_t)(Tst * Vt) + 2 * l) = o1;
        }
        __syncthreads();   // D: lg/b2s/W2/RS readers done before t+1 writes
    }
}

extern "C" void kernel_launch(void* const* d_in, const int* in_sizes, int n_in,
                              void* d_out, int out_size)
{
    const float* latent0   = (const float*)d_in[0];
    const float* W1        = (const float*)d_in[1];
    const float* b1        = (const float*)d_in[2];
    const float* W2        = (const float*)d_in[3];
    const float* b2        = (const float*)d_in[4];
    const int*   state_seq = (const int*)  d_in[5];
    const int*   out_idx   = (const int*)  d_in[6];
    float* out = (float*)d_out;

    split_w12<<<2048, 512>>>(W1, W2);

    cudaFuncSetAttribute(lalr_all, cudaFuncAttributeMaxDynamicSharedMemorySize, SMEMB);
    lalr_all<<<Bsz / MT, 512, SMEMB>>>(
        latent0, W1, b1, W2, b2, state_seq, out_idx, out);
}

// round 16
// speedup vs baseline: 1.6415x; 1.6415x over previous
#include <cuda_runtime.h>
#include <cuda_bf16.h>
#include <cstdint>

#define Bsz 4096
#define Tst 128
#define NL  256
#define NSt 64
#define NOt 32
#define Vt  64
#define MT  32
#define XR  264        // x row stride (bf16)
#define NCH 16
#define SLG 36
#define W2R 264        // w2 smem row stride (bf16)

typedef uint32_t u32;

__device__ __nv_bfloat16 g_w1h[(size_t)NSt * NL * NL];
__device__ __nv_bfloat16 g_w1l[(size_t)NSt * NL * NL];
__device__ __nv_bfloat16 g_w2h[(size_t)NSt * NOt * NL];
__device__ __nv_bfloat16 g_w2l[(size_t)NSt * NOt * NL];

__device__ __forceinline__ u32 s2u(const void* p) {
    return (u32)__cvta_generic_to_shared(p);
}
__device__ __forceinline__ void ldsm4(u32* r, u32 a) {
    asm volatile("ldmatrix.sync.aligned.m8n8.x4.shared.b16 {%0,%1,%2,%3}, [%4];"
        : "=r"(r[0]), "=r"(r[1]), "=r"(r[2]), "=r"(r[3]) : "r"(a));
}
__device__ __forceinline__ void mma16(float* c, const u32* a, u32 b0, u32 b1) {
    asm volatile("mma.sync.aligned.m16n8k16.row.col.f32.bf16.bf16.f32 "
        "{%0,%1,%2,%3},{%4,%5,%6,%7},{%8,%9},{%0,%1,%2,%3};"
        : "+f"(c[0]), "+f"(c[1]), "+f"(c[2]), "+f"(c[3])
        : "r"(a[0]), "r"(a[1]), "r"(a[2]), "r"(a[3]), "r"(b0), "r"(b1));
}
__device__ __forceinline__ void cpa16(u32 dst, const void* src) {
    asm volatile("cp.async.cg.shared.global [%0], [%1], 16;"
        :: "r"(dst), "l"(src) : "memory");
}
#define CPA_COMMIT() asm volatile("cp.async.commit_group;" ::: "memory")
#define CPA_WAIT4()  asm volatile("cp.async.wait_group 4;" ::: "memory")

// Fast branch-free tanh: |abs err| <~ 2^-21, no overflow.
__device__ __forceinline__ float ftanh(float x) {
    float t = __expf(-2.f * fabsf(x));
    float r = __fdividef(1.f - t, 1.f + t);
    return copysignf(r, x);
}

__device__ __forceinline__ void sp(__nv_bfloat16* xh, __nv_bfloat16* xl, int idx,
                                   float v0, float v1) {
    __nv_bfloat16 h0 = __float2bfloat16(v0), h1 = __float2bfloat16(v1);
    __nv_bfloat162 hp; hp.x = h0; hp.y = h1;
    *(__nv_bfloat162*)(xh + idx) = hp;
    __nv_bfloat162 lp;
    lp.x = __float2bfloat16(v0 - __bfloat162float(h0));
    lp.y = __float2bfloat16(v1 - __bfloat162float(h1));
    *(__nv_bfloat162*)(xl + idx) = lp;
}

// smem byte offsets (identical budget to R14; YB -> DON)
#define OB_XH0 0                 // [32][XR] bf16  16896
#define OB_XL0 16896
#define OB_XH1 33792             // second x buffer
#define OB_XL1 50688
#define OB_W1S 67584             // 16 warps x 6 stages x (512 hi + 512 lo) = 98304
#define OB_W2H 165888            // 16896
#define OB_W2L 182784            // 16896
#define OB_RS  199680            // [4][32][36] f32 = 18432
#define OB_LG  218112            // 4608
#define OB_DON 222720            // 16 warps x 64 i32 = 4096
#define OB_B2  226816            // 2 x 32 f32 (double-buffered)
#define OB_SQ  227072            // 512
#define SMEMB  227584

__global__ void split_w12(const float* __restrict__ W1, const float* __restrict__ W2) {
    const size_t n1 = (size_t)NSt * NL * NL;
    for (size_t i = blockIdx.x * blockDim.x + threadIdx.x; i < n1;
         i += (size_t)gridDim.x * blockDim.x) {
        float x = W1[i];
        __nv_bfloat16 h = __float2bfloat16(x);
        g_w1h[i] = h;
        g_w1l[i] = __float2bfloat16(x - __bfloat162float(h));
    }
    const size_t n2 = (size_t)NSt * NOt * NL;
    for (size_t i = blockIdx.x * blockDim.x + threadIdx.x; i < n2;
         i += (size_t)gridDim.x * blockDim.x) {
        float x = W2[i];
        __nv_bfloat16 h = __float2bfloat16(x);
        g_w2h[i] = h;
        g_w2l[i] = __float2bfloat16(x - __bfloat162float(h));
    }
}

__global__ void __launch_bounds__(512, 1) lalr_all(
    const float* __restrict__ latent0,
    const float* __restrict__ W1, const float* __restrict__ b1,
    const float* __restrict__ W2, const float* __restrict__ b2,
    const int*   __restrict__ state_seq, const int* __restrict__ out_idx,
    float* __restrict__ out)
{
    extern __shared__ char smc[];
    float* rs  = (float*)(smc + OB_RS);
    float* lg  = (float*)(smc + OB_LG);
    float* b2s = (float*)(smc + OB_B2);
    int*  sseq = (int*)(smc + OB_SQ);

    const int tid = threadIdx.x;
    const int w = tid >> 5, l = tid & 31;
    const int rowbase = blockIdx.x * MT;
    const int gid = l >> 2, tg = l & 3;

    // A fragment lane mapping — proven idiom
    const int arow = l & 15;
    const int akof = (l >> 4) * 8;
    // B fragment lane mapping — proven idiom
    const int bn = ((l >> 4) & 1) * 8 + (l & 7);
    const int bk = (l >> 3) & 1;
    // GEMM1 B read offset in packed+swizzled stage (warp owns 16 cols, 512B/arr)
    const u32 bo = (u32)((bn * 32 + bk * 16) ^ (((bn >> 2) & 1) << 4));
    // W1 cp.async fill mapping: lane -> col fn, k-half (l>>4)
    const int fn = l & 15;
    const u32 fil = (u32)((fn * 32 + (l >> 4) * 16) ^ (((fn >> 2) & 1) << 4));
    const u32 wstage = s2u(smc + OB_W1S + w * 6144);   // 6 stages x 1024B
    // W2 fill / GEMM2 mappings (proven)
    const int bofs264 = (bn * W2R + bk * 8) * 2;
    const int o2 = tid & 31, kq2 = (tid >> 5) * 16;
    const int mi2 = w & 1, nh = (w >> 1) & 1, kg = w >> 2;
    const u32 w2dh = s2u(smc + OB_W2H) + (u32)((o2 * W2R + kq2) * 2);
    const u32 w2dl = s2u(smc + OB_W2L) + (u32)((o2 * W2R + kq2) * 2);

    // ---- init ----
    if (tid < Tst) sseq[tid] = state_seq[tid];
    {
        __nv_bfloat16* xh0 = (__nv_bfloat16*)(smc + OB_XH0);
        __nv_bfloat16* xl0 = (__nv_bfloat16*)(smc + OB_XL0);
        int r = tid >> 4, kc = (tid & 15) * 16;
        const float* src = latent0 + (size_t)(rowbase + r) * NL + kc;
        #pragma unroll
        for (int j = 0; j < 16; j += 2)
            sp(xh0 + r * XR + kc, xl0 + r * XR + kc, j, src[j], src[j + 1]);
    }
    __syncthreads();

    // W1 chunk issuer: explicit stage, packed 512B layout
    auto issue_w1 = [&](int ig, size_t base, int stg) {
        if (ig < Tst * NCH) {
            size_t off = base + ((size_t)(ig & 15) << 4);
            u32 d = wstage + (u32)stg * 1024u;
            cpa16(d + fil, g_w1h + off);
            cpa16(d + 512 + fil, g_w1l + off);
        }
        CPA_COMMIT();
    };
    // W2 stage via cp.async (one group; 64B hi + 64B lo per thread)
    auto issue_w2 = [&](int sw2) {
        const __nv_bfloat16* sh = g_w2h + ((size_t)sw2 * NOt + o2) * NL + kq2;
        const __nv_bfloat16* sl = g_w2l + ((size_t)sw2 * NOt + o2) * NL + kq2;
        cpa16(w2dh, sh);      cpa16(w2dh + 16, sh + 8);
        cpa16(w2dl, sl);      cpa16(w2dl + 16, sl + 8);
        CPA_COMMIT();
    };

    // ---- prologue: issue W1 chunks 0..4 (stages 0..4) ----
    int s = sseq[0];
    size_t base_cur = ((size_t)s * NL + w * 16 + fn) * NL + (l >> 4) * 8;
    issue_w1(0, base_cur, 0);
    issue_w1(1, base_cur, 1);
    issue_w1(2, base_cur, 2);
    issue_w1(3, base_cur, 3);
    issue_w1(4, base_cur, 4);
    int istg = 5, rstg = 0;

    float b2r = (tid < NOt) ? b2[s * NOt + tid] : 0.f;

    for (int t = 0; t < Tst; t++) {
        char* xcb = smc + (t & 1) * 33792;
        char* xnb = smc + ((t & 1) ^ 1) * 33792;
        __nv_bfloat16* xh_c = (__nv_bfloat16*)(xcb + OB_XH0);
        __nv_bfloat16* xl_c = (__nv_bfloat16*)(xcb + OB_XL0);
        __nv_bfloat16* xh_n = (__nv_bfloat16*)(xnb + OB_XH0);
        __nv_bfloat16* xl_n = (__nv_bfloat16*)(xnb + OB_XL0);

        float2 bias0 = *(const float2*)(b1 + s * NL + w * 16 + 2 * tg);
        float2 bias1 = *(const float2*)(b1 + s * NL + w * 16 + 8 + 2 * tg);
        int idxv = out_idx[s * NOt + l];
        const int s_nxt = sseq[(t + 1) & (Tst - 1)];
        const size_t base_nxt = ((size_t)s_nxt * NL + w * 16 + fn) * NL + (l >> 4) * 8;

        // W2 -> smem via cp.async (one group; completes during GEMM1 waits)
        issue_w2(s);
        if (tid < NOt) b2s[(t & 1) * 32 + tid] = b2r;

        // ---- GEMM1: 3-term bf16 split MMA, fragment-double-buffered ----
        float acc[2][2][4];
        #pragma unroll
        for (int mi = 0; mi < 2; mi++)
            #pragma unroll
            for (int ni = 0; ni < 2; ni++)
                #pragma unroll
                for (int j = 0; j < 4; j++) acc[mi][ni][j] = 0.f;

        const u32 aHb = s2u(xh_c + arow * XR + akof);
        const u32 aLb = s2u(xl_c + arow * XR + akof);

        u32 AH0[2][4], AH1[2][4], AL0[2][4], AL1[2][4], BH[2][4], BL[2][4];

        // preload chunk 0 of this step
        CPA_WAIT4();
        __syncwarp();
        {
            u32 wb = wstage + (u32)rstg * 1024u;
            rstg = (rstg == 5) ? 0 : rstg + 1;
            ldsm4(BH[0], wb + bo);
            ldsm4(BL[0], wb + 512 + bo);
            ldsm4(AH0[0], aHb);
            ldsm4(AH1[0], aHb + 16 * XR * 2);
            ldsm4(AL0[0], aLb);
            ldsm4(AL1[0], aLb + 16 * XR * 2);
        }

        #pragma unroll
        for (int kt = 0; kt < NCH; kt++) {
            const int cur = kt & 1, nxt = cur ^ 1;
            // keep 5 W1 chunks in flight
            issue_w1(t * NCH + kt + 5, (kt + 5 < NCH) ? base_cur : base_nxt, istg);
            istg = (istg == 5) ? 0 : istg + 1;
            if (kt + 1 < NCH) {
                CPA_WAIT4();
                __syncwarp();
                const u32 ka = (u32)((kt + 1) * 32);
                u32 wb = wstage + (u32)rstg * 1024u;
                rstg = (rstg == 5) ? 0 : rstg + 1;
                ldsm4(BH[nxt], wb + bo);
                ldsm4(BL[nxt], wb + 512 + bo);
                ldsm4(AH0[nxt], aHb + ka);
                ldsm4(AH1[nxt], aHb + ka + 16 * XR * 2);
                ldsm4(AL0[nxt], aLb + ka);
                ldsm4(AL1[nxt], aLb + ka + 16 * XR * 2);
            }
            const u32 *ah0 = AH0[cur], *ah1 = AH1[cur];
            const u32 *al0 = AL0[cur], *al1 = AL1[cur];
            const u32 *bh = BH[cur], *bl = BL[cur];
            mma16(acc[0][0], ah0, bh[0], bh[1]); mma16(acc[0][1], ah0, bh[2], bh[3]);
            mma16(acc[1][0], ah1, bh[0], bh[1]); mma16(acc[1][1], ah1, bh[2], bh[3]);
            mma16(acc[0][0], ah0, bl[0], bl[1]); mma16(acc[0][1], ah0, bl[2], bl[3]);
            mma16(acc[1][0], ah1, bl[0], bl[1]); mma16(acc[1][1], ah1, bl[2], bl[3]);
            mma16(acc[0][0], al0, bh[0], bh[1]); mma16(acc[0][1], al0, bh[2], bh[3]);
            mma16(acc[1][0], al1, bh[0], bh[1]); mma16(acc[1][1], al1, bh[2], bh[3]);
        }

        // ---- tail prefetch for t+1 (b2 only; W1/W2 handled by cp.async) ----
        b2r = (tid < NOt) ? b2[s_nxt * NOt + tid] : 0.f;
        s = s_nxt;
        base_cur = base_nxt;

        // ---- epilogue: fast tanh + bf16 split -> NEXT x buffer ----
        #pragma unroll
        for (int mi = 0; mi < 2; mi++)
            #pragma unroll
            for (int ni = 0; ni < 2; ni++) {
                float2 bias = ni ? bias1 : bias0;
                float* c = acc[mi][ni];
                int cp = w * 16 + ni * 8 + 2 * tg;
                int r0 = mi * 16 + gid;
                sp(xh_n, xl_n, r0 * XR + cp, ftanh(c[0] + bias.x), ftanh(c[1] + bias.y));
                sp(xh_n, xl_n, (r0 + 8) * XR + cp, ftanh(c[2] + bias.x), ftanh(c[3] + bias.y));
            }
        __syncthreads();   // B: x_{t+1} + w2/b2 smem ready

        // ---- GEMM2 via MMA: warp = m16(mi2) x n16(nh) x k64(kg), 3-term ----
        {
            float c2[2][4];
            #pragma unroll
            for (int j = 0; j < 2; j++)
                #pragma unroll
                for (int q = 0; q < 4; q++) c2[j][q] = 0.f;

            const u32 a2h = s2u(xh_n + (mi2 * 16 + arow) * XR + kg * 64 + akof);
            const u32 a2l = s2u(xl_n + (mi2 * 16 + arow) * XR + kg * 64 + akof);
            const u32 b2hB = s2u(smc + OB_W2H) + nh * 16 * W2R * 2 + bofs264 + kg * 128;
            const u32 b2lB = s2u(smc + OB_W2L) + nh * 16 * W2R * 2 + bofs264 + kg * 128;

            #pragma unroll
            for (int kc = 0; kc < 4; kc++) {
                const u32 kb = (u32)(kc * 32);
                u32 ah[4], al[4], bh[4], bl[4];
                ldsm4(ah, a2h + kb);
                ldsm4(al, a2l + kb);
                ldsm4(bh, b2hB + kb);
                ldsm4(bl, b2lB + kb);
                mma16(c2[0], ah, bh[0], bh[1]); mma16(c2[1], ah, bh[2], bh[3]);
                mma16(c2[0], ah, bl[0], bl[1]); mma16(c2[1], ah, bl[2], bl[3]);
                mma16(c2[0], al, bh[0], bh[1]); mma16(c2[1], al, bh[2], bh[3]);
            }
            #pragma unroll
            for (int j = 0; j < 2; j++) {
                float* dst = rs + (kg * 32 + mi2 * 16 + gid) * 36 + nh * 16 + j * 8 + 2 * tg;
                float2 lo; lo.x = c2[j][0]; lo.y = c2[j][1];
                float2 hi; hi.x = c2[j][2]; hi.y = c2[j][3];
                *(float2*)dst = lo;
                *(float2*)(dst + 8 * 36) = hi;
            }
        }
        __syncthreads();   // C: partials ready

        // ---- split-k reduce -> logits ----
        {
            int rrow = 2 * w + (l >> 4);
            int cc = (l & 15) * 2;
            const float* bb = b2s + (t & 1) * 32;
            float2 sum; sum.x = bb[cc]; sum.y = bb[cc + 1];
            #pragma unroll
            for (int kg2 = 0; kg2 < 4; kg2++) {
                float2 v = *(const float2*)(rs + (kg2 * 32 + rrow) * 36 + cc);
                sum.x += v.x; sum.y += v.y;
            }
            *(float2*)(lg + rrow * SLG + cc) = sum;
        }
        __syncwarp();

        // ---- softmax (2 rows interleaved) + donor-table scatter + store ----
        {
            int* don = (int*)(smc + OB_DON) + w * 64;
            don[l] = -1; don[l + 32] = -1;
            __syncwarp();
            unsigned mset = __match_any_sync(0xffffffffu, idxv);
            bool leader = (31 - __clz(mset)) == l;
            if (leader) don[idxv] = l;
            __syncwarp();
            int d0 = don[2 * l], d1 = don[2 * l + 1];

            float v0 = lg[(2 * w) * SLG + l];
            float v1 = lg[(2 * w + 1) * SLG + l];
            float m0 = v0, m1 = v1;
            #pragma unroll
            for (int off = 16; off > 0; off >>= 1) {
                m0 = fmaxf(m0, __shfl_xor_sync(0xffffffffu, m0, off));
                m1 = fmaxf(m1, __shfl_xor_sync(0xffffffffu, m1, off));
            }
            float e0 = __expf(v0 - m0), e1 = __expf(v1 - m1);
            float s0 = e0, s1 = e1;
            #pragma unroll
            for (int off = 16; off > 0; off >>= 1) {
                s0 += __shfl_xor_sync(0xffffffffu, s0, off);
                s1 += __shfl_xor_sync(0xffffffffu, s1, off);
            }
            float p0 = __fdividef(e0, s0), p1 = __fdividef(e1, s1);

            float a0 = __shfl_sync(0xffffffffu, p0, d0 & 31);
            float a1 = __shfl_sync(0xffffffffu, p0, d1 & 31);
            float b0 = __shfl_sync(0xffffffffu, p1, d0 & 31);
            float b1v = __shfl_sync(0xffffffffu, p1, d1 & 31);
            float2 o0, o1;
            o0.x = (d0 >= 0) ? a0 : 0.f; o0.y = (d1 >= 0) ? a1 : 0.f;
            o1.x = (d0 >= 0) ? b0 : 0.f; o1.y = (d1 >= 0) ? b1v : 0.f;
            float* op0 = out + (size_t)(rowbase + 2 * w) * (Tst * Vt) + (size_t)t * Vt;
            *(float2*)(op0 + 2 * l) = o0;
            *(float2*)(op0 + (size_t)(Tst * Vt) + 2 * l) = o1;
        }
        // next-step smem writes gated by barriers B/C of next iteration
        // (W2 cp.async of t+1 targets memory whose readers finished before C(t))
    }
}

extern "C" void kernel_launch(void* const* d_in, const int* in_sizes, int n_in,
                              void* d_out, int out_size)
{
    const float* latent0   = (const float*)d_in[0];
    const float* W1        = (const float*)d_in[1];
    const float* b1        = (const float*)d_in[2];
    const float* W2        = (const float*)d_in[3];
    const float* b2        = (const float*)d_in[4];
    const int*   state_seq = (const int*)  d_in[5];
    const int*   out_idx   = (const int*)  d_in[6];
    float* out = (float*)d_out;

    split_w12<<<2048, 512>>>(W1, W2);

    cudaFuncSetAttribute(lalr_all, cudaFuncAttributeMaxDynamicSharedMemorySize, SMEMB);
    lalr_all<<<Bsz / MT, 512, SMEMB>>>(
        latent0, W1, b1, W2, b2, state_seq, out_idx, out);
}